// round 1
// baseline (speedup 1.0000x reference)
#include <cuda_runtime.h>
#include <math.h>

// Problem constants
#define BATCH 4096
#define NNOTES 48
#define NFEAT 256
#define NU 256          // hidden units
#define NG 1024         // 4*NU gate width
#define MTOT (BATCH * NNOTES)   // 196608

// GEMM tiling
#define BM 128
#define BN 128
#define BK 16

// ------------------- device scratch (no runtime allocs allowed) -------------------
__device__ float g_xg0[(size_t)NNOTES * BATCH * NG];     // precomputed input gates, layer 0  (805 MB)
__device__ float g_h1all[(size_t)NNOTES * BATCH * NU];   // h1 per step (201 MB)
__device__ float g_gates[BATCH * NG];                    // per-step gate scratch (16 MB)
__device__ float g_h0[BATCH * NU];
__device__ float g_c0[BATCH * NU];
__device__ float g_h1[BATCH * NU];
__device__ float g_c1[BATCH * NU];
__device__ float g_wcat[NG * 512];    // [W_ih1 | W_hh1] concatenated along K (2 MB)
__device__ float g_w0main[NG * 256];  // W_ih0[:, :256] repacked contiguous (1 MB)
__device__ float g_w0ext[NG * 4];     // W_ih0[:, 256:259] padded to 4
__device__ float g_bias0[NG];
__device__ float g_bias1[NG];

__device__ __forceinline__ float sigf(float x) { return 1.0f / (1.0f + expf(-x)); }

// ------------------- prep: repack weights, sum biases, zero state -------------------
__global__ void prep_kernel(const float* __restrict__ W_ih0,
                            const float* __restrict__ W_ih1,
                            const float* __restrict__ W_hh1,
                            const float* __restrict__ b_ih0,
                            const float* __restrict__ b_hh0,
                            const float* __restrict__ b_ih1,
                            const float* __restrict__ b_hh1) {
    int tid = blockIdx.x * blockDim.x + threadIdx.x;
    int stride = gridDim.x * blockDim.x;
    // W_ih0 main block (row stride 259 -> 256)
    for (int i = tid; i < NG * 256; i += stride) {
        int j = i >> 8, k = i & 255;
        g_w0main[i] = W_ih0[j * 259 + k];
    }
    // Concatenated layer-1 weights [NG, 512]
    for (int i = tid; i < NG * 512; i += stride) {
        int j = i >> 9, k = i & 511;
        g_wcat[i] = (k < 256) ? W_ih1[j * 256 + k] : W_hh1[j * 256 + (k - 256)];
    }
    // Extra 3 columns of W_ih0 (padded)
    for (int i = tid; i < NG * 4; i += stride) {
        int j = i >> 2, t = i & 3;
        g_w0ext[i] = (t < 3) ? W_ih0[j * 259 + 256 + t] : 0.0f;
    }
    // Bias sums
    for (int i = tid; i < NG; i += stride) {
        g_bias0[i] = b_ih0[i] + b_hh0[i];
        g_bias1[i] = b_ih1[i] + b_hh1[i];
    }
    // Zero initial state
    for (int i = tid; i < BATCH * NU; i += stride) {
        g_h0[i] = 0.0f; g_c0[i] = 0.0f; g_h1[i] = 0.0f; g_c1[i] = 0.0f;
    }
}

// ------------------- big precompute GEMM: g_xg0 = x_all @ W_ih0^T + bias0 -------------------
// M = 196608 rows (m = n*4096 + b), N = 1024, K = 256 (main) + 3 (epilogue)
__global__ void __launch_bounds__(256) gemm_xg0(const float* __restrict__ nf,
                                                const float* __restrict__ cn) {
    __shared__ float As[BK][BM + 4];
    __shared__ float Bs[BK][BN + 4];

    const int bm = blockIdx.y * BM;
    const int bn = blockIdx.x * BN;
    const int t = threadIdx.x;
    const int lrow = t >> 2;
    const int lc4 = (t & 3) * 4;
    const int tx = t & 15, ty = t >> 4;
    const int row0 = ty * 4, row1 = 64 + ty * 4;
    const int col0 = tx * 4, col1 = 64 + tx * 4;

    // Hoist per-thread A row pointers (rows fixed across K loop)
    const float* arow[2];
#pragma unroll
    for (int h = 0; h < 2; h++) {
        int m = bm + lrow + h * 64;
        int b = m & 4095, n = m >> 12;
        arow[h] = nf + (size_t)b * (NNOTES * NFEAT) + (size_t)n * NFEAT;
    }

    float acc[8][8];
#pragma unroll
    for (int i = 0; i < 8; i++)
#pragma unroll
        for (int j = 0; j < 8; j++) acc[i][j] = 0.0f;

    for (int k0 = 0; k0 < 256; k0 += BK) {
#pragma unroll
        for (int h = 0; h < 2; h++) {
            float4 v = *reinterpret_cast<const float4*>(arow[h] + k0 + lc4);
            int r = lrow + h * 64;
            As[lc4 + 0][r] = v.x; As[lc4 + 1][r] = v.y;
            As[lc4 + 2][r] = v.z; As[lc4 + 3][r] = v.w;
        }
#pragma unroll
        for (int h = 0; h < 2; h++) {
            int j = bn + lrow + h * 64;
            float4 v = *reinterpret_cast<const float4*>(&g_w0main[j * 256 + k0 + lc4]);
            int r = lrow + h * 64;
            Bs[lc4 + 0][r] = v.x; Bs[lc4 + 1][r] = v.y;
            Bs[lc4 + 2][r] = v.z; Bs[lc4 + 3][r] = v.w;
        }
        __syncthreads();
#pragma unroll
        for (int k = 0; k < BK; k++) {
            float a[8], bv[8];
            *reinterpret_cast<float4*>(&a[0]) = *reinterpret_cast<const float4*>(&As[k][row0]);
            *reinterpret_cast<float4*>(&a[4]) = *reinterpret_cast<const float4*>(&As[k][row1]);
            *reinterpret_cast<float4*>(&bv[0]) = *reinterpret_cast<const float4*>(&Bs[k][col0]);
            *reinterpret_cast<float4*>(&bv[4]) = *reinterpret_cast<const float4*>(&Bs[k][col1]);
#pragma unroll
            for (int i = 0; i < 8; i++)
#pragma unroll
                for (int j = 0; j < 8; j++) acc[i][j] += a[i] * bv[j];
        }
        __syncthreads();
    }

    // Epilogue: + bias0 + shifted-notes (3 cols) contribution; store to g_xg0
#pragma unroll
    for (int i = 0; i < 8; i++) {
        int m = bm + ((i < 4) ? (row0 + i) : (row1 + i - 4));
        int b = m & 4095, n = m >> 12;
        float s0 = 0.0f, s1 = 0.0f, s2 = 0.0f;
        if (n > 0) {
            const float* p = cn + (size_t)b * (NNOTES * 3) + (size_t)(n - 1) * 3;
            s0 = p[0]; s1 = p[1]; s2 = p[2];
        }
#pragma unroll
        for (int jh = 0; jh < 2; jh++) {
            int ncc = bn + ((jh == 0) ? col0 : col1);
            float4 v;
            v.x = acc[i][jh * 4 + 0]; v.y = acc[i][jh * 4 + 1];
            v.z = acc[i][jh * 4 + 2]; v.w = acc[i][jh * 4 + 3];
            v.x += g_bias0[ncc + 0] + s0 * g_w0ext[(ncc + 0) * 4 + 0] + s1 * g_w0ext[(ncc + 0) * 4 + 1] + s2 * g_w0ext[(ncc + 0) * 4 + 2];
            v.y += g_bias0[ncc + 1] + s0 * g_w0ext[(ncc + 1) * 4 + 0] + s1 * g_w0ext[(ncc + 1) * 4 + 1] + s2 * g_w0ext[(ncc + 1) * 4 + 2];
            v.z += g_bias0[ncc + 2] + s0 * g_w0ext[(ncc + 2) * 4 + 0] + s1 * g_w0ext[(ncc + 2) * 4 + 1] + s2 * g_w0ext[(ncc + 2) * 4 + 2];
            v.w += g_bias0[ncc + 3] + s0 * g_w0ext[(ncc + 3) * 4 + 0] + s1 * g_w0ext[(ncc + 3) * 4 + 1] + s2 * g_w0ext[(ncc + 3) * 4 + 2];
            *reinterpret_cast<float4*>(&g_xg0[(size_t)m * NG + ncc]) = v;
        }
    }
}

// ------------------- recurrent GEMM -------------------
// mode 0 (layer 0): g_gates = g_h0 @ W_hh0^T + g_xg0[n]          (K=256, Bw = W_hh0 input)
// mode 1 (layer 1): g_gates = [g_h0|g_h1] @ g_wcat^T + g_bias1   (K=512)
__global__ void __launch_bounds__(256) gemm_rec(const float* __restrict__ Wext, int mode, int n) {
    __shared__ float As[BK][BM + 4];
    __shared__ float Bs[BK][BN + 4];

    const int bm = blockIdx.y * BM;
    const int bn = blockIdx.x * BN;
    const int t = threadIdx.x;
    const int lrow = t >> 2;
    const int lc4 = (t & 3) * 4;
    const int tx = t & 15, ty = t >> 4;
    const int row0 = ty * 4, row1 = 64 + ty * 4;
    const int col0 = tx * 4, col1 = 64 + tx * 4;

    const int K = (mode == 0) ? 256 : 512;
    const float* Bw = (mode == 0) ? Wext : g_wcat;

    float acc[8][8];
#pragma unroll
    for (int i = 0; i < 8; i++)
#pragma unroll
        for (int j = 0; j < 8; j++) acc[i][j] = 0.0f;

    const int m0 = bm + lrow;
    const int m1 = bm + lrow + 64;

    for (int k0 = 0; k0 < K; k0 += BK) {
        // A tile: pick h0 for k<256, h1 for k>=256 (mode 1)
        {
            const float* src = (k0 < 256) ? g_h0 : g_h1;
            int kloc = (k0 < 256) ? (k0 + lc4) : (k0 - 256 + lc4);
            float4 v0 = *reinterpret_cast<const float4*>(&src[m0 * 256 + kloc]);
            float4 v1 = *reinterpret_cast<const float4*>(&src[m1 * 256 + kloc]);
            As[lc4 + 0][lrow] = v0.x; As[lc4 + 1][lrow] = v0.y;
            As[lc4 + 2][lrow] = v0.z; As[lc4 + 3][lrow] = v0.w;
            As[lc4 + 0][lrow + 64] = v1.x; As[lc4 + 1][lrow + 64] = v1.y;
            As[lc4 + 2][lrow + 64] = v1.z; As[lc4 + 3][lrow + 64] = v1.w;
        }
#pragma unroll
        for (int h = 0; h < 2; h++) {
            int j = bn + lrow + h * 64;
            float4 v = *reinterpret_cast<const float4*>(&Bw[(size_t)j * K + k0 + lc4]);
            int r = lrow + h * 64;
            Bs[lc4 + 0][r] = v.x; Bs[lc4 + 1][r] = v.y;
            Bs[lc4 + 2][r] = v.z; Bs[lc4 + 3][r] = v.w;
        }
        __syncthreads();
#pragma unroll
        for (int k = 0; k < BK; k++) {
            float a[8], bv[8];
            *reinterpret_cast<float4*>(&a[0]) = *reinterpret_cast<const float4*>(&As[k][row0]);
            *reinterpret_cast<float4*>(&a[4]) = *reinterpret_cast<const float4*>(&As[k][row1]);
            *reinterpret_cast<float4*>(&bv[0]) = *reinterpret_cast<const float4*>(&Bs[k][col0]);
            *reinterpret_cast<float4*>(&bv[4]) = *reinterpret_cast<const float4*>(&Bs[k][col1]);
#pragma unroll
            for (int i = 0; i < 8; i++)
#pragma unroll
                for (int j = 0; j < 8; j++) acc[i][j] += a[i] * bv[j];
        }
        __syncthreads();
    }

    const size_t xoff = (size_t)n * BATCH * NG;
#pragma unroll
    for (int i = 0; i < 8; i++) {
        int m = bm + ((i < 4) ? (row0 + i) : (row1 + i - 4));
#pragma unroll
        for (int jh = 0; jh < 2; jh++) {
            int ncc = bn + ((jh == 0) ? col0 : col1);
            float4 v;
            v.x = acc[i][jh * 4 + 0]; v.y = acc[i][jh * 4 + 1];
            v.z = acc[i][jh * 4 + 2]; v.w = acc[i][jh * 4 + 3];
            if (mode == 0) {
                float4 ad = *reinterpret_cast<const float4*>(&g_xg0[xoff + (size_t)m * NG + ncc]);
                v.x += ad.x; v.y += ad.y; v.z += ad.z; v.w += ad.w;
            } else {
                v.x += g_bias1[ncc + 0]; v.y += g_bias1[ncc + 1];
                v.z += g_bias1[ncc + 2]; v.w += g_bias1[ncc + 3];
            }
            *reinterpret_cast<float4*>(&g_gates[m * NG + ncc]) = v;
        }
    }
}

// ------------------- pointwise LSTM cells -------------------
__global__ void pointwise0() {
    int idx = blockIdx.x * blockDim.x + threadIdx.x;   // 0 .. BATCH*NU-1
    int b = idx >> 8, u = idx & 255;
    const float* g = &g_gates[b * NG];
    float ig = g[u], fg = g[u + 256], gg = g[u + 512], og = g[u + 768];
    float c = g_c0[idx];
    float cn_ = sigf(fg) * c + sigf(ig) * tanhf(gg);
    g_c0[idx] = cn_;
    g_h0[idx] = sigf(og) * tanhf(cn_);
}

__global__ void pointwise1(int n) {
    int idx = blockIdx.x * blockDim.x + threadIdx.x;
    int b = idx >> 8, u = idx & 255;
    const float* g = &g_gates[b * NG];
    float ig = g[u], fg = g[u + 256], gg = g[u + 512], og = g[u + 768];
    float c = g_c1[idx];
    float cn_ = sigf(fg) * c + sigf(ig) * tanhf(gg);
    g_c1[idx] = cn_;
    float h = sigf(og) * tanhf(cn_);
    g_h1[idx] = h;
    g_h1all[(size_t)n * (BATCH * NU) + idx] = h;
}

// ------------------- final projection: out = h1_all @ W_out^T + b_out, sigmoid first 2 -------------------
__global__ void final_out(const float* __restrict__ Wout, const float* __restrict__ bout,
                          float* __restrict__ out) {
    int gwarp = (blockIdx.x * blockDim.x + threadIdx.x) >> 5;
    int lane = threadIdx.x & 31;
    if (gwarp >= MTOT) return;
    int b = gwarp / NNOTES, n = gwarp % NNOTES;
    const float* hrow = &g_h1all[(size_t)n * (BATCH * NU) + (size_t)b * NU];

    float s0 = 0.0f, s1 = 0.0f, s2 = 0.0f;
    int u = lane * 8;
    float4 v0 = *reinterpret_cast<const float4*>(&hrow[u]);
    float4 v1 = *reinterpret_cast<const float4*>(&hrow[u + 4]);
    float hv[8] = {v0.x, v0.y, v0.z, v0.w, v1.x, v1.y, v1.z, v1.w};
#pragma unroll
    for (int i = 0; i < 8; i++) {
        float h = hv[i];
        s0 += h * Wout[0 * NU + u + i];
        s1 += h * Wout[1 * NU + u + i];
        s2 += h * Wout[2 * NU + u + i];
    }
#pragma unroll
    for (int off = 16; off > 0; off >>= 1) {
        s0 += __shfl_xor_sync(0xffffffffu, s0, off);
        s1 += __shfl_xor_sync(0xffffffffu, s1, off);
        s2 += __shfl_xor_sync(0xffffffffu, s2, off);
    }
    if (lane == 0) {
        float* o = &out[(size_t)b * (NNOTES * 3) + (size_t)n * 3];
        o[0] = sigf(s0 + bout[0]);
        o[1] = sigf(s1 + bout[1]);
        o[2] = s2 + bout[2];
    }
}

// ------------------- launch -------------------
extern "C" void kernel_launch(void* const* d_in, const int* in_sizes, int n_in,
                              void* d_out, int out_size) {
    const float* nf    = (const float*)d_in[0];
    const float* cn    = (const float*)d_in[1];
    const float* W_ih0 = (const float*)d_in[2];
    const float* W_hh0 = (const float*)d_in[3];
    const float* b_ih0 = (const float*)d_in[4];
    const float* b_hh0 = (const float*)d_in[5];
    const float* W_ih1 = (const float*)d_in[6];
    const float* W_hh1 = (const float*)d_in[7];
    const float* b_ih1 = (const float*)d_in[8];
    const float* b_hh1 = (const float*)d_in[9];
    const float* W_out = (const float*)d_in[10];
    const float* b_out = (const float*)d_in[11];
    float* out = (float*)d_out;

    prep_kernel<<<256, 256>>>(W_ih0, W_ih1, W_hh1, b_ih0, b_hh0, b_ih1, b_hh1);

    // Precompute all input-gate contributions for layer 0
    gemm_xg0<<<dim3(NG / BN, MTOT / BM), 256>>>(nf, cn);

    dim3 gridRec(NG / BN, BATCH / BM);   // (8, 32)
    int pwBlocks = (BATCH * NU) / 256;   // 4096
    for (int n = 0; n < NNOTES; n++) {
        gemm_rec<<<gridRec, 256>>>(W_hh0, 0, n);
        pointwise0<<<pwBlocks, 256>>>();
        gemm_rec<<<gridRec, 256>>>(nullptr, 1, n);
        pointwise1<<<pwBlocks, 256>>>(n);
    }

    int warps = MTOT;                          // one warp per (b, n)
    int blocks = (warps * 32 + 255) / 256;     // 24576
    final_out<<<blocks, 256>>>(W_out, b_out, out);
}

// round 3
// speedup vs baseline: 1.2470x; 1.2470x over previous
#include <cuda_runtime.h>
#include <cuda_bf16.h>
#include <stdint.h>
#include <math.h>

#define BATCH 4096
#define NNOTES 48
#define NU 256
#define NG 1024
#define MTOT (BATCH * NNOTES)

// ------------------- device scratch -------------------
__device__ float g_xg0[(size_t)NNOTES * BATCH * NG];     // precomputed layer-0 input gates (permuted cols)
__device__ float g_h1all[(size_t)NNOTES * BATCH * NU];   // h1 per step (fp32, for final projection)
__device__ float g_c0[BATCH * NU];
__device__ float g_c1[BATCH * NU];
__device__ __nv_bfloat16 g_h0h[2][BATCH * NU];           // h0 hi, double-buffered by step parity
__device__ __nv_bfloat16 g_h0l[2][BATCH * NU];           // h0 lo
__device__ __nv_bfloat16 g_h1h[2][BATCH * NU];
__device__ __nv_bfloat16 g_h1l[2][BATCH * NU];
// weights, permuted rows + split hi/lo bf16
__device__ __nv_bfloat16 g_w0h[NG * 256], g_w0l[NG * 256];       // W_ih0[:, :256]
__device__ __nv_bfloat16 g_whh0h[NG * 256], g_whh0l[NG * 256];   // W_hh0
__device__ __nv_bfloat16 g_wcath[NG * 512], g_wcatl[NG * 512];   // [W_ih1 | W_hh1]
__device__ float g_w0ext[NG * 4];     // W_ih0[:, 256:259] permuted, padded
__device__ float g_bias0[NG];
__device__ float g_bias1[NG];

__device__ __forceinline__ float sigf(float x) { return 1.0f / (1.0f + expf(-x)); }

// Column permutation: GEMM output column c -> original gate row R.
// Within each 64-wide warp tile, unit gates are placed so one thread's mma
// accumulator fragments hold complete (i,f,g,o) quadruples.
__device__ __forceinline__ int permR(int c) {
    int W = c >> 6, cc = c & 63;
    int f = cc >> 3, r = cc & 7;
    int tig = r >> 1, e = r & 1;
    int v = (f & 3) * 4 + tig;
    int gate = (f >> 2) * 2 + e;
    int u = W * 16 + v;
    return gate * 256 + u;
}

__device__ __forceinline__ void split_bf16(float x, __nv_bfloat16& hi, __nv_bfloat16& lo) {
    hi = __float2bfloat16_rn(x);
    lo = __float2bfloat16_rn(x - __bfloat162float(hi));
}

// ------------------- prep -------------------
__global__ void prep_kernel(const float* __restrict__ W_ih0,
                            const float* __restrict__ W_hh0,
                            const float* __restrict__ W_ih1,
                            const float* __restrict__ W_hh1,
                            const float* __restrict__ b_ih0,
                            const float* __restrict__ b_hh0,
                            const float* __restrict__ b_ih1,
                            const float* __restrict__ b_hh1) {
    int tid = blockIdx.x * blockDim.x + threadIdx.x;
    int stride = gridDim.x * blockDim.x;
    for (int i = tid; i < NG * 256; i += stride) {
        int c = i >> 8, k = i & 255, R = permR(c);
        split_bf16(W_ih0[R * 259 + k], g_w0h[i], g_w0l[i]);
        split_bf16(W_hh0[R * 256 + k], g_whh0h[i], g_whh0l[i]);
    }
    for (int i = tid; i < NG * 512; i += stride) {
        int c = i >> 9, k = i & 511, R = permR(c);
        float x = (k < 256) ? W_ih1[R * 256 + k] : W_hh1[R * 256 + (k - 256)];
        split_bf16(x, g_wcath[i], g_wcatl[i]);
    }
    for (int i = tid; i < NG * 4; i += stride) {
        int c = i >> 2, t = i & 3, R = permR(c);
        g_w0ext[i] = (t < 3) ? W_ih0[R * 259 + 256 + t] : 0.0f;
    }
    for (int i = tid; i < NG; i += stride) {
        int R = permR(i);
        g_bias0[i] = b_ih0[R] + b_hh0[R];
        g_bias1[i] = b_ih1[R] + b_hh1[R];
    }
    __nv_bfloat16 z = __float2bfloat16(0.0f);
    for (int i = tid; i < BATCH * NU; i += stride) {
        g_c0[i] = 0.0f; g_c1[i] = 0.0f;
        g_h0h[0][i] = z; g_h0l[0][i] = z;
        g_h1h[0][i] = z; g_h1l[0][i] = z;
    }
}

// ------------------- mma helpers -------------------
__device__ __forceinline__ void ldsm_x4(uint32_t addr, uint32_t& r0, uint32_t& r1,
                                        uint32_t& r2, uint32_t& r3) {
    asm volatile("ldmatrix.sync.aligned.m8n8.x4.shared.b16 {%0,%1,%2,%3}, [%4];"
                 : "=r"(r0), "=r"(r1), "=r"(r2), "=r"(r3) : "r"(addr));
}

__device__ __forceinline__ void mma_bf16(float* d, const uint32_t* a, const uint32_t* b) {
    asm volatile(
        "mma.sync.aligned.m16n8k16.row.col.f32.bf16.bf16.f32 "
        "{%0,%1,%2,%3},{%4,%5,%6,%7},{%8,%9},{%0,%1,%2,%3};"
        : "+f"(d[0]), "+f"(d[1]), "+f"(d[2]), "+f"(d[3])
        : "r"(a[0]), "r"(a[1]), "r"(a[2]), "r"(a[3]), "r"(b[0]), "r"(b[1]));
}

// ------------------- unified GEMM + fused epilogue -------------------
// MODE 0: g_xg0 = x_all @ W0^T + bias0 (+ ext cols), M=196608, K=256
// MODE 1: layer-0 recurrent: gates = h0 @ Whh0^T + xg0[n]; fused LSTM cell -> h0, c0
// MODE 2: layer-1: gates = [h0|h1] @ Wcat^T + bias1; fused cell -> h1, c1, h1all
template <int MODE>
__global__ void __launch_bounds__(256) mma_gemm(const float* __restrict__ nf,
                                                const float* __restrict__ cn,
                                                int n) {
    constexpr int KTOT = (MODE == 2) ? 512 : 256;
    constexpr int NCHUNK = KTOT / 16;
    constexpr int RS = 24;  // smem row stride in halves (conflict-free for ldmatrix)

    __shared__ __nv_bfloat16 sA[2][128 * RS];
    __shared__ __nv_bfloat16 sB[2][128 * RS];

    const int t = threadIdx.x;
    const int bm = blockIdx.y * 128;
    const int bn = blockIdx.x * 128;
    const int lrow = t >> 1;
    const int lk8 = (t & 1) * 8;
    const int lane = t & 31, warp = t >> 5;
    const int wm = warp & 3, wn = warp >> 2;

    // staged global loads
    float4 fa0, fa1;
    uint4 ra_h, ra_l, rb_h, rb_l;

    auto loadA = [&](int ck) {
        int kk = ck * 16 + lk8;
        if (MODE == 0) {
            int m = bm + lrow;
            int b = m & 4095, nn = m >> 12;
            const float4* p = reinterpret_cast<const float4*>(
                nf + (((size_t)b * NNOTES + nn) << 8) + kk);
            fa0 = p[0]; fa1 = p[1];
        } else if (MODE == 1) {
            size_t off = (size_t)(bm + lrow) * 256 + kk;
            ra_h = *reinterpret_cast<const uint4*>(&g_h0h[n & 1][off]);
            ra_l = *reinterpret_cast<const uint4*>(&g_h0l[n & 1][off]);
        } else {
            if (kk < 256) {
                size_t off = (size_t)(bm + lrow) * 256 + kk;
                ra_h = *reinterpret_cast<const uint4*>(&g_h0h[(n & 1) ^ 1][off]);
                ra_l = *reinterpret_cast<const uint4*>(&g_h0l[(n & 1) ^ 1][off]);
            } else {
                size_t off = (size_t)(bm + lrow) * 256 + (kk - 256);
                ra_h = *reinterpret_cast<const uint4*>(&g_h1h[n & 1][off]);
                ra_l = *reinterpret_cast<const uint4*>(&g_h1l[n & 1][off]);
            }
        }
    };
    auto loadB = [&](int ck) {
        int kk = ck * 16 + lk8;
        size_t off = (size_t)(bn + lrow) * KTOT + kk;
        const __nv_bfloat16* sh = (MODE == 0) ? g_w0h : (MODE == 1) ? g_whh0h : g_wcath;
        const __nv_bfloat16* sl = (MODE == 0) ? g_w0l : (MODE == 1) ? g_whh0l : g_wcatl;
        rb_h = *reinterpret_cast<const uint4*>(&sh[off]);
        rb_l = *reinterpret_cast<const uint4*>(&sl[off]);
    };
    auto storeStage = [&]() {
        int off = lrow * RS + lk8;
        if (MODE == 0) {
            float v[8] = {fa0.x, fa0.y, fa0.z, fa0.w, fa1.x, fa1.y, fa1.z, fa1.w};
            union { __nv_bfloat16 b[8]; uint4 u; } uh, ul;
#pragma unroll
            for (int i = 0; i < 8; i++) split_bf16(v[i], uh.b[i], ul.b[i]);
            *reinterpret_cast<uint4*>(&sA[0][off]) = uh.u;
            *reinterpret_cast<uint4*>(&sA[1][off]) = ul.u;
        } else {
            *reinterpret_cast<uint4*>(&sA[0][off]) = ra_h;
            *reinterpret_cast<uint4*>(&sA[1][off]) = ra_l;
        }
        *reinterpret_cast<uint4*>(&sB[0][off]) = rb_h;
        *reinterpret_cast<uint4*>(&sB[1][off]) = rb_l;
    };

    // ldmatrix addresses (invariant across chunks)
    uint32_t aAddr[2][2], bAddr[2][4];
#pragma unroll
    for (int hl = 0; hl < 2; hl++) {
        uint32_t baseA = (uint32_t)__cvta_generic_to_shared(&sA[hl][0]);
        uint32_t baseB = (uint32_t)__cvta_generic_to_shared(&sB[hl][0]);
#pragma unroll
        for (int mi = 0; mi < 2; mi++)
            aAddr[hl][mi] = baseA +
                ((wm * 32 + mi * 16 + (lane & 15)) * RS + (lane >> 4) * 8) * 2;
#pragma unroll
        for (int fp = 0; fp < 4; fp++)
            bAddr[hl][fp] = baseB +
                ((wn * 64 + fp * 16 + (lane >> 4) * 8 + (lane & 7)) * RS +
                 ((lane >> 3) & 1) * 8) * 2;
    }

    float acc[2][8][4];
#pragma unroll
    for (int mi = 0; mi < 2; mi++)
#pragma unroll
        for (int f = 0; f < 8; f++)
#pragma unroll
            for (int x = 0; x < 4; x++) acc[mi][f][x] = 0.0f;

    loadA(0); loadB(0);
    for (int ck = 0; ck < NCHUNK; ck++) {
        __syncthreads();
        storeStage();
        __syncthreads();
        if (ck + 1 < NCHUNK) { loadA(ck + 1); loadB(ck + 1); }

        uint32_t Ah[2][4], Al[2][4];
#pragma unroll
        for (int mi = 0; mi < 2; mi++) {
            ldsm_x4(aAddr[0][mi], Ah[mi][0], Ah[mi][1], Ah[mi][2], Ah[mi][3]);
            ldsm_x4(aAddr[1][mi], Al[mi][0], Al[mi][1], Al[mi][2], Al[mi][3]);
        }
#pragma unroll
        for (int fp = 0; fp < 4; fp++) {
            uint32_t Bh[4], Bl[4];
            ldsm_x4(bAddr[0][fp], Bh[0], Bh[1], Bh[2], Bh[3]);
            ldsm_x4(bAddr[1][fp], Bl[0], Bl[1], Bl[2], Bl[3]);
#pragma unroll
            for (int mi = 0; mi < 2; mi++) {
                mma_bf16(acc[mi][2 * fp + 0], Ah[mi], &Bh[0]);
                mma_bf16(acc[mi][2 * fp + 0], Ah[mi], &Bl[0]);
                mma_bf16(acc[mi][2 * fp + 0], Al[mi], &Bh[0]);
                mma_bf16(acc[mi][2 * fp + 1], Ah[mi], &Bh[2]);
                mma_bf16(acc[mi][2 * fp + 1], Ah[mi], &Bl[2]);
                mma_bf16(acc[mi][2 * fp + 1], Al[mi], &Bh[2]);
            }
        }
    }

    // ------------- fused epilogue -------------
    if (MODE == 0) {
        int rowm[4];
        float sv[4][3];
#pragma unroll
        for (int rid = 0; rid < 4; rid++) {
            int mi = rid >> 1, rh = rid & 1;
            int m = bm + wm * 32 + mi * 16 + rh * 8 + (lane >> 2);
            rowm[rid] = m;
            int b = m & 4095, nn = m >> 12;
            if (nn > 0) {
                const float* p = cn + ((size_t)b * NNOTES + (nn - 1)) * 3;
                sv[rid][0] = p[0]; sv[rid][1] = p[1]; sv[rid][2] = p[2];
            } else {
                sv[rid][0] = sv[rid][1] = sv[rid][2] = 0.0f;
            }
        }
#pragma unroll
        for (int f = 0; f < 8; f++) {
            int c = bn + wn * 64 + 8 * f + 2 * (lane & 3);
            float2 bia = *reinterpret_cast<const float2*>(&g_bias0[c]);
            float4 e0 = *reinterpret_cast<const float4*>(&g_w0ext[(size_t)c * 4]);
            float4 e1 = *reinterpret_cast<const float4*>(&g_w0ext[(size_t)(c + 1) * 4]);
#pragma unroll
            for (int rid = 0; rid < 4; rid++) {
                int mi = rid >> 1, rh = rid & 1;
                float2 o;
                o.x = acc[mi][f][rh * 2 + 0] + bia.x +
                      sv[rid][0] * e0.x + sv[rid][1] * e0.y + sv[rid][2] * e0.z;
                o.y = acc[mi][f][rh * 2 + 1] + bia.y +
                      sv[rid][0] * e1.x + sv[rid][1] * e1.y + sv[rid][2] * e1.z;
                *reinterpret_cast<float2*>(&g_xg0[(size_t)rowm[rid] * NG + c]) = o;
            }
        }
    } else {
        const int outp = (n & 1) ^ 1;
#pragma unroll
        for (int rid = 0; rid < 4; rid++) {
            int mi = rid >> 1, rh = rid & 1;
            int m = bm + wm * 32 + mi * 16 + rh * 8 + (lane >> 2);
#pragma unroll
            for (int v = 0; v < 4; v++) {
                int cif = bn + wn * 64 + 8 * v + 2 * (lane & 3);
                float2 aif, ago;
                if (MODE == 1) {
                    const float* xb = g_xg0 + (size_t)n * ((size_t)BATCH * NG) + (size_t)m * NG;
                    aif = *reinterpret_cast<const float2*>(&xb[cif]);
                    ago = *reinterpret_cast<const float2*>(&xb[cif + 32]);
                } else {
                    aif = *reinterpret_cast<const float2*>(&g_bias1[cif]);
                    ago = *reinterpret_cast<const float2*>(&g_bias1[cif + 32]);
                }
                float gi = acc[mi][v][rh * 2 + 0] + aif.x;
                float gf = acc[mi][v][rh * 2 + 1] + aif.y;
                float gg = acc[mi][v + 4][rh * 2 + 0] + ago.x;
                float go = acc[mi][v + 4][rh * 2 + 1] + ago.y;
                int u = ((bn + wn * 64) >> 6) * 16 + v * 4 + (lane & 3);
                int idx = m * 256 + u;
                float* cptr = (MODE == 1) ? g_c0 : g_c1;
                float cp = cptr[idx];
                float cnew = sigf(gf) * cp + sigf(gi) * tanhf(gg);
                float h = sigf(go) * tanhf(cnew);
                cptr[idx] = cnew;
                __nv_bfloat16 hh = __float2bfloat16_rn(h);
                __nv_bfloat16 hl = __float2bfloat16_rn(h - __bfloat162float(hh));
                if (MODE == 1) {
                    g_h0h[outp][idx] = hh; g_h0l[outp][idx] = hl;
                } else {
                    g_h1h[outp][idx] = hh; g_h1l[outp][idx] = hl;
                    g_h1all[(size_t)n * (BATCH * NU) + idx] = h;
                }
            }
        }
    }
}

// ------------------- final projection -------------------
__global__ void final_out(const float* __restrict__ Wout, const float* __restrict__ bout,
                          float* __restrict__ out) {
    int gwarp = (blockIdx.x * blockDim.x + threadIdx.x) >> 5;
    int lane = threadIdx.x & 31;
    if (gwarp >= MTOT) return;
    int b = gwarp / NNOTES, n = gwarp % NNOTES;
    const float* hrow = &g_h1all[(size_t)n * (BATCH * NU) + (size_t)b * NU];

    float s0 = 0.0f, s1 = 0.0f, s2 = 0.0f;
    int u = lane * 8;
    float4 v0 = *reinterpret_cast<const float4*>(&hrow[u]);
    float4 v1 = *reinterpret_cast<const float4*>(&hrow[u + 4]);
    float hv[8] = {v0.x, v0.y, v0.z, v0.w, v1.x, v1.y, v1.z, v1.w};
#pragma unroll
    for (int i = 0; i < 8; i++) {
        float h = hv[i];
        s0 += h * Wout[0 * NU + u + i];
        s1 += h * Wout[1 * NU + u + i];
        s2 += h * Wout[2 * NU + u + i];
    }
#pragma unroll
    for (int off = 16; off > 0; off >>= 1) {
        s0 += __shfl_xor_sync(0xffffffffu, s0, off);
        s1 += __shfl_xor_sync(0xffffffffu, s1, off);
        s2 += __shfl_xor_sync(0xffffffffu, s2, off);
    }
    if (lane == 0) {
        float* o = &out[(size_t)b * (NNOTES * 3) + (size_t)n * 3];
        o[0] = sigf(s0 + bout[0]);
        o[1] = sigf(s1 + bout[1]);
        o[2] = s2 + bout[2];
    }
}

// ------------------- launch -------------------
extern "C" void kernel_launch(void* const* d_in, const int* in_sizes, int n_in,
                              void* d_out, int out_size) {
    const float* nf    = (const float*)d_in[0];
    const float* cn    = (const float*)d_in[1];
    const float* W_ih0 = (const float*)d_in[2];
    const float* W_hh0 = (const float*)d_in[3];
    const float* b_ih0 = (const float*)d_in[4];
    const float* b_hh0 = (const float*)d_in[5];
    const float* W_ih1 = (const float*)d_in[6];
    const float* W_hh1 = (const float*)d_in[7];
    const float* b_ih1 = (const float*)d_in[8];
    const float* b_hh1 = (const float*)d_in[9];
    const float* W_out = (const float*)d_in[10];
    const float* b_out = (const float*)d_in[11];
    float* out = (float*)d_out;

    prep_kernel<<<256, 256>>>(W_ih0, W_hh0, W_ih1, W_hh1, b_ih0, b_hh0, b_ih1, b_hh1);

    // Precompute all layer-0 input gate contributions (permuted cols)
    mma_gemm<0><<<dim3(NG / 128, MTOT / 128), 256>>>(nf, cn, 0);

    dim3 gridRec(NG / 128, BATCH / 128);   // (8, 32)
    for (int n = 0; n < NNOTES; n++) {
        mma_gemm<1><<<gridRec, 256>>>(nullptr, nullptr, n);
        mma_gemm<2><<<gridRec, 256>>>(nullptr, nullptr, n);
    }

    int blocks = (MTOT * 32 + 255) / 256;
    final_out<<<blocks, 256>>>(W_out, b_out, out);
}

// round 5
// speedup vs baseline: 1.6582x; 1.3297x over previous
#include <cuda_runtime.h>
#include <cuda_bf16.h>
#include <stdint.h>
#include <math.h>

#define BATCH 4096
#define NNOTES 48
#define NU 256
#define NG 1024
#define MTOT (BATCH * NNOTES)

// ==================== device scratch ====================
__device__ float g_xg0[(size_t)NNOTES * BATCH * NG];     // layer-0 input preactivations (permuted cols)
__device__ float g_h1all[(size_t)NNOTES * BATCH * NU];   // h1 per step (fp32)
__device__ float g_c0[BATCH * NU];
__device__ float g_c1[BATCH * NU];
__device__ __align__(128) __nv_bfloat16 g_h0h[2][BATCH * NU];   // h0 hi, double-buffered by parity
__device__ __align__(128) __nv_bfloat16 g_h0l[2][BATCH * NU];
__device__ __align__(128) __nv_bfloat16 g_h1h[2][BATCH * NU];
__device__ __align__(128) __nv_bfloat16 g_h1l[2][BATCH * NU];
// x input split hi/lo, row m = n*4096+b, 256 wide
__device__ __align__(128) __nv_bfloat16 g_xh[(size_t)MTOT * 256];
__device__ __align__(128) __nv_bfloat16 g_xl[(size_t)MTOT * 256];
// weights, permuted rows, split hi/lo, row-major [c][K]
__device__ __align__(128) __nv_bfloat16 g_w0h[NG * 256], g_w0l[NG * 256];       // W_ih0[:, :256]
__device__ __align__(128) __nv_bfloat16 g_whh0h[NG * 256], g_whh0l[NG * 256];   // W_hh0
__device__ __align__(128) __nv_bfloat16 g_wcath[NG * 512], g_wcatl[NG * 512];   // [W_ih1 | W_hh1]
__device__ float g_w0ext[NG * 4];
__device__ float g_bias0[NG];
__device__ float g_bias1[NG];

__device__ __forceinline__ float sigf(float x) { return 1.0f / (1.0f + expf(-x)); }

// Gate-column permutation (same as R3, verified): GEMM col c -> original row R
__device__ __forceinline__ int permR(int c) {
    int W = c >> 6, cc = c & 63;
    int f = cc >> 3, r = cc & 7;
    int tig = r >> 1, e = r & 1;
    int v = (f & 3) * 4 + tig;
    int gate = (f >> 2) * 2 + e;
    int u = W * 16 + v;
    return gate * 256 + u;
}

__device__ __forceinline__ void split_bf16(float x, __nv_bfloat16& hi, __nv_bfloat16& lo) {
    hi = __float2bfloat16_rn(x);
    lo = __float2bfloat16_rn(x - __bfloat162float(hi));
}
union BF8 { __nv_bfloat16 b[8]; uint4 u; };

// ==================== prep kernels ====================
__global__ void prep_w(const float* __restrict__ W_ih0,
                       const float* __restrict__ W_hh0,
                       const float* __restrict__ W_ih1,
                       const float* __restrict__ W_hh1,
                       const float* __restrict__ b_ih0,
                       const float* __restrict__ b_hh0,
                       const float* __restrict__ b_ih1,
                       const float* __restrict__ b_hh1) {
    int tid = blockIdx.x * blockDim.x + threadIdx.x;
    int stride = gridDim.x * blockDim.x;
    for (int i = tid; i < NG * 256; i += stride) {
        int c = i >> 8, k = i & 255, R = permR(c);
        split_bf16(W_ih0[R * 259 + k], g_w0h[i], g_w0l[i]);
        split_bf16(W_hh0[R * 256 + k], g_whh0h[i], g_whh0l[i]);
    }
    for (int i = tid; i < NG * 512; i += stride) {
        int c = i >> 9, k = i & 511, R = permR(c);
        float x = (k < 256) ? W_ih1[R * 256 + k] : W_hh1[R * 256 + (k - 256)];
        split_bf16(x, g_wcath[i], g_wcatl[i]);
    }
    for (int i = tid; i < NG * 4; i += stride) {
        int c = i >> 2, t = i & 3, R = permR(c);
        g_w0ext[i] = (t < 3) ? W_ih0[R * 259 + 256 + t] : 0.0f;
    }
    for (int i = tid; i < NG; i += stride) {
        int R = permR(i);
        g_bias0[i] = b_ih0[R] + b_hh0[R];
        g_bias1[i] = b_ih1[R] + b_hh1[R];
    }
    __nv_bfloat16 z = __float2bfloat16(0.0f);
    for (int i = tid; i < BATCH * NU; i += stride) {
        g_c0[i] = 0.0f; g_c1[i] = 0.0f;
        g_h0h[0][i] = z; g_h0l[0][i] = z;
        g_h1h[0][i] = z; g_h1l[0][i] = z;
    }
}

// split x into bf16 hi/lo with row m = n*4096+b
__global__ void prep_x(const float* __restrict__ nf) {
    size_t idx = (size_t)blockIdx.x * blockDim.x + threadIdx.x;  // MTOT*32 threads
    if (idx >= (size_t)MTOT * 32) return;
    int k8 = (int)(idx & 31) * 8;
    int m = (int)(idx >> 5);
    int b = m & 4095, nn = m >> 12;
    const float* src = nf + (((size_t)b * NNOTES + nn) << 8) + k8;
    float4 a = *(const float4*)src, c4 = *(const float4*)(src + 4);
    float v[8] = {a.x, a.y, a.z, a.w, c4.x, c4.y, c4.z, c4.w};
    BF8 hh, ll;
#pragma unroll
    for (int i = 0; i < 8; i++) split_bf16(v[i], hh.b[i], ll.b[i]);
    *(uint4*)&g_xh[(size_t)m * 256 + k8] = hh.u;
    *(uint4*)&g_xl[(size_t)m * 256 + k8] = ll.u;
}

// ==================== mma / cp.async helpers ====================
__device__ __forceinline__ uint32_t smem_u32(const void* p) {
    uint32_t a;
    asm("{ .reg .u64 t; cvta.to.shared.u64 t, %1; cvt.u32.u64 %0, t; }" : "=r"(a) : "l"(p));
    return a;
}
__device__ __forceinline__ void cpa16(uint32_t dst, const void* src) {
    asm volatile("cp.async.cg.shared.global [%0], [%1], 16;" :: "r"(dst), "l"(src) : "memory");
}
__device__ __forceinline__ void ldsm_x4(uint32_t addr, uint32_t& r0, uint32_t& r1,
                                        uint32_t& r2, uint32_t& r3) {
    asm volatile("ldmatrix.sync.aligned.m8n8.x4.shared.b16 {%0,%1,%2,%3}, [%4];"
                 : "=r"(r0), "=r"(r1), "=r"(r2), "=r"(r3) : "r"(addr));
}
__device__ __forceinline__ void mma_bf16(float* d, const uint32_t* a, const uint32_t* b) {
    asm volatile(
        "mma.sync.aligned.m16n8k16.row.col.f32.bf16.bf16.f32 "
        "{%0,%1,%2,%3},{%4,%5,%6,%7},{%8,%9},{%0,%1,%2,%3};"
        : "+f"(d[0]), "+f"(d[1]), "+f"(d[2]), "+f"(d[3])
        : "r"(a[0]), "r"(a[1]), "r"(a[2]), "r"(a[3]), "r"(b[0]), "r"(b[1]));
}

// ==================== unified GEMM + fused LSTM epilogue ====================
// Split-2 via K-concat: C = Ah.Bh + Ah.Bl + Al.Bh as one K'=3K GEMM.
// MODE 0: xg0 = x @ W0^T + bias0 + ext, M=196608, K'=768
// MODE 1: gates = h0 @ Whh0^T + xg0[n]; LSTM -> h0,c0.  K'=768
// MODE 2: gates = [h0|h1] @ Wcat^T + bias1; LSTM -> h1,c1,h1all.  K'=1536
// CTA tile 128x128, 8 warps (4 M-strips x 2 N-strips), BK=32, 4-stage cp.async.
#define STAGE_BYTES 20480   // A(128*80) + B(128*80)
template <int MODE>
__global__ void __launch_bounds__(256, 2) mma_gemm(const float* __restrict__ cn, int n) {
    constexpr int NCH = (MODE == 2) ? 48 : 24;
    extern __shared__ __align__(128) char dynsmem[];
    const uint32_t smem_base = smem_u32(dynsmem);

    const int t = threadIdx.x;
    const int bm = blockIdx.y * 128;
    const int bn = blockIdx.x * 128;
    const int lane = t & 31, warp = t >> 5;
    const int wm = warp & 3, wn = warp >> 2;
    const int seg = t & 3, r0 = t >> 2;   // loader mapping: 2 rows x 16B per thread per tile
    const int pPrev = n & 1, pNew = (n & 1) ^ 1;

    auto issue = [&](int ck, int s) {
        const char *Asrc, *Bsrc;
        int kkA, kkB;
        size_t bpitch;
        if (MODE == 0) {
            int term = ck >> 3, kk = (ck & 7) * 32;
            Asrc = (const char*)((term < 2) ? g_xh : g_xl);
            Bsrc = (const char*)((term == 1) ? g_w0l : g_w0h);
            kkA = kk; kkB = kk; bpitch = 512;
        } else if (MODE == 1) {
            int term = ck >> 3, kk = (ck & 7) * 32;
            Asrc = (const char*)((term < 2) ? g_h0h[pPrev] : g_h0l[pPrev]);
            Bsrc = (const char*)((term == 1) ? g_whh0l : g_whh0h);
            kkA = kk; kkB = kk; bpitch = 512;
        } else {
            int term = ck >> 4, kk = (ck & 15) * 32;
            bool lo = (term == 2);
            if (kk < 256) {
                Asrc = (const char*)(lo ? g_h0l[pNew] : g_h0h[pNew]);
                kkA = kk;
            } else {
                Asrc = (const char*)(lo ? g_h1l[pPrev] : g_h1h[pPrev]);
                kkA = kk - 256;
            }
            Bsrc = (const char*)((term == 1) ? g_wcatl : g_wcath);
            kkB = kk; bpitch = 1024;
        }
        uint32_t dA = smem_base + s * STAGE_BYTES;
        uint32_t dB = dA + 10240;
#pragma unroll
        for (int h = 0; h < 2; h++) {
            int row = r0 + h * 64;
            cpa16(dA + row * 80 + seg * 16,
                  Asrc + (size_t)(bm + row) * 512 + kkA * 2 + seg * 16);
            cpa16(dB + row * 80 + seg * 16,
                  Bsrc + (size_t)(bn + row) * bpitch + kkB * 2 + seg * 16);
        }
        asm volatile("cp.async.commit_group;" ::: "memory");
    };

    float acc[2][8][4];
#pragma unroll
    for (int mi = 0; mi < 2; mi++)
#pragma unroll
        for (int f = 0; f < 8; f++)
#pragma unroll
            for (int x = 0; x < 4; x++) acc[mi][f][x] = 0.0f;

    // prologue: 3 stages in flight
    issue(0, 0); issue(1, 1); issue(2, 2);

    for (int ck = 0; ck < NCH; ck++) {
        if (ck + 3 < NCH) issue(ck + 3, (ck + 3) & 3);
        int rem = NCH - 1 - ck;
        if (rem >= 3)      asm volatile("cp.async.wait_group 3;" ::: "memory");
        else if (rem == 2) asm volatile("cp.async.wait_group 2;" ::: "memory");
        else if (rem == 1) asm volatile("cp.async.wait_group 1;" ::: "memory");
        else               asm volatile("cp.async.wait_group 0;" ::: "memory");
        __syncthreads();

        uint32_t sAb = smem_base + (ck & 3) * STAGE_BYTES;
        uint32_t sBb = sAb + 10240;
#pragma unroll
        for (int ks = 0; ks < 2; ks++) {
            uint32_t A[2][4];
#pragma unroll
            for (int mi = 0; mi < 2; mi++) {
                uint32_t addr = sAb + (wm * 32 + mi * 16 + (lane & 15)) * 80 +
                                ks * 32 + (lane >> 4) * 16;
                ldsm_x4(addr, A[mi][0], A[mi][1], A[mi][2], A[mi][3]);
            }
#pragma unroll
            for (int fp = 0; fp < 4; fp++) {
                uint32_t B[4];
                uint32_t addr = sBb + (wn * 64 + fp * 16 + (lane >> 4) * 8 + (lane & 7)) * 80 +
                                ks * 32 + ((lane >> 3) & 1) * 16;
                ldsm_x4(addr, B[0], B[1], B[2], B[3]);
#pragma unroll
                for (int mi = 0; mi < 2; mi++) {
                    mma_bf16(acc[mi][2 * fp + 0], A[mi], &B[0]);
                    mma_bf16(acc[mi][2 * fp + 1], A[mi], &B[2]);
                }
            }
        }
        __syncthreads();
    }

    // ------------- fused epilogue (verified in R3) -------------
    if (MODE == 0) {
        int rowm[4];
        float sv[4][3];
#pragma unroll
        for (int rid = 0; rid < 4; rid++) {
            int mi = rid >> 1, rh = rid & 1;
            int m = bm + wm * 32 + mi * 16 + rh * 8 + (lane >> 2);
            rowm[rid] = m;
            int b = m & 4095, nn = m >> 12;
            if (nn > 0) {
                const float* p = cn + ((size_t)b * NNOTES + (nn - 1)) * 3;
                sv[rid][0] = p[0]; sv[rid][1] = p[1]; sv[rid][2] = p[2];
            } else {
                sv[rid][0] = sv[rid][1] = sv[rid][2] = 0.0f;
            }
        }
#pragma unroll
        for (int f = 0; f < 8; f++) {
            int c = bn + wn * 64 + 8 * f + 2 * (lane & 3);
            float2 bia = *(const float2*)&g_bias0[c];
            float4 e0 = *(const float4*)&g_w0ext[(size_t)c * 4];
            float4 e1 = *(const float4*)&g_w0ext[(size_t)(c + 1) * 4];
#pragma unroll
            for (int rid = 0; rid < 4; rid++) {
                int mi = rid >> 1, rh = rid & 1;
                float2 o;
                o.x = acc[mi][f][rh * 2 + 0] + bia.x +
                      sv[rid][0] * e0.x + sv[rid][1] * e0.y + sv[rid][2] * e0.z;
                o.y = acc[mi][f][rh * 2 + 1] + bia.y +
                      sv[rid][0] * e1.x + sv[rid][1] * e1.y + sv[rid][2] * e1.z;
                *(float2*)&g_xg0[(size_t)rowm[rid] * NG + c] = o;
            }
        }
    } else {
#pragma unroll
        for (int rid = 0; rid < 4; rid++) {
            int mi = rid >> 1, rh = rid & 1;
            int m = bm + wm * 32 + mi * 16 + rh * 8 + (lane >> 2);
#pragma unroll
            for (int v = 0; v < 4; v++) {
                int cif = bn + wn * 64 + 8 * v + 2 * (lane & 3);
                float2 aif, ago;
                if (MODE == 1) {
                    const float* xb = g_xg0 + (size_t)n * ((size_t)BATCH * NG) + (size_t)m * NG;
                    aif = *(const float2*)&xb[cif];
                    ago = *(const float2*)&xb[cif + 32];
                } else {
                    aif = *(const float2*)&g_bias1[cif];
                    ago = *(const float2*)&g_bias1[cif + 32];
                }
                float gi = acc[mi][v][rh * 2 + 0] + aif.x;
                float gf = acc[mi][v][rh * 2 + 1] + aif.y;
                float gg = acc[mi][v + 4][rh * 2 + 0] + ago.x;
                float go = acc[mi][v + 4][rh * 2 + 1] + ago.y;
                int u = ((bn + wn * 64) >> 6) * 16 + v * 4 + (lane & 3);
                int idx = m * 256 + u;
                float* cptr = (MODE == 1) ? g_c0 : g_c1;
                float cp = cptr[idx];
                float cnew = sigf(gf) * cp + sigf(gi) * tanhf(gg);
                float h = sigf(go) * tanhf(cnew);
                cptr[idx] = cnew;
                __nv_bfloat16 hh = __float2bfloat16_rn(h);
                __nv_bfloat16 hl = __float2bfloat16_rn(h - __bfloat162float(hh));
                if (MODE == 1) {
                    g_h0h[pNew][idx] = hh; g_h0l[pNew][idx] = hl;
                } else {
                    g_h1h[pNew][idx] = hh; g_h1l[pNew][idx] = hl;
                    g_h1all[(size_t)n * (BATCH * NU) + idx] = h;
                }
            }
        }
    }
}

// ==================== final projection ====================
__global__ void final_out(const float* __restrict__ Wout, const float* __restrict__ bout,
                          float* __restrict__ out) {
    int gwarp = (blockIdx.x * blockDim.x + threadIdx.x) >> 5;
    int lane = threadIdx.x & 31;
    if (gwarp >= MTOT) return;
    int b = gwarp / NNOTES, n = gwarp % NNOTES;
    const float* hrow = &g_h1all[(size_t)n * (BATCH * NU) + (size_t)b * NU];

    float s0 = 0.0f, s1 = 0.0f, s2 = 0.0f;
    int u = lane * 8;
    float4 v0 = *(const float4*)&hrow[u];
    float4 v1 = *(const float4*)&hrow[u + 4];
    float hv[8] = {v0.x, v0.y, v0.z, v0.w, v1.x, v1.y, v1.z, v1.w};
#pragma unroll
    for (int i = 0; i < 8; i++) {
        float h = hv[i];
        s0 += h * Wout[0 * NU + u + i];
        s1 += h * Wout[1 * NU + u + i];
        s2 += h * Wout[2 * NU + u + i];
    }
#pragma unroll
    for (int off = 16; off > 0; off >>= 1) {
        s0 += __shfl_xor_sync(0xffffffffu, s0, off);
        s1 += __shfl_xor_sync(0xffffffffu, s1, off);
        s2 += __shfl_xor_sync(0xffffffffu, s2, off);
    }
    if (lane == 0) {
        float* o = &out[(size_t)b * (NNOTES * 3) + (size_t)n * 3];
        o[0] = sigf(s0 + bout[0]);
        o[1] = sigf(s1 + bout[1]);
        o[2] = s2 + bout[2];
    }
}

// ==================== launch ====================
extern "C" void kernel_launch(void* const* d_in, const int* in_sizes, int n_in,
                              void* d_out, int out_size) {
    const float* nf    = (const float*)d_in[0];
    const float* cn    = (const float*)d_in[1];
    const float* W_ih0 = (const float*)d_in[2];
    const float* W_hh0 = (const float*)d_in[3];
    const float* b_ih0 = (const float*)d_in[4];
    const float* b_hh0 = (const float*)d_in[5];
    const float* W_ih1 = (const float*)d_in[6];
    const float* W_hh1 = (const float*)d_in[7];
    const float* b_ih1 = (const float*)d_in[8];
    const float* b_hh1 = (const float*)d_in[9];
    const float* W_out = (const float*)d_in[10];
    const float* b_out = (const float*)d_in[11];
    float* out = (float*)d_out;

    const int DYNSMEM = 4 * STAGE_BYTES;  // 81920
    cudaFuncSetAttribute(mma_gemm<0>, cudaFuncAttributeMaxDynamicSharedMemorySize, DYNSMEM);
    cudaFuncSetAttribute(mma_gemm<1>, cudaFuncAttributeMaxDynamicSharedMemorySize, DYNSMEM);
    cudaFuncSetAttribute(mma_gemm<2>, cudaFuncAttributeMaxDynamicSharedMemorySize, DYNSMEM);

    prep_w<<<1024, 256>>>(W_ih0, W_hh0, W_ih1, W_hh1, b_ih0, b_hh0, b_ih1, b_hh1);
    prep_x<<<(MTOT * 32 + 255) / 256, 256>>>(nf);

    // layer-0 input GEMM over all notes
    mma_gemm<0><<<dim3(NG / 128, MTOT / 128), 256, DYNSMEM>>>(cn, 0);

    dim3 gridRec(NG / 128, BATCH / 128);   // (8, 32)
    for (int n = 0; n < NNOTES; n++) {
        mma_gemm<1><<<gridRec, 256, DYNSMEM>>>(nullptr, n);
        mma_gemm<2><<<gridRec, 256, DYNSMEM>>>(nullptr, n);
    }

    int blocks = (MTOT * 32 + 255) / 256;
    final_out<<<blocks, 256>>>(W_out, b_out, out);
}

// round 6
// speedup vs baseline: 1.8479x; 1.1144x over previous
#include <cuda_runtime.h>
#include <cuda_bf16.h>
#include <stdint.h>
#include <math.h>

#define BATCH 4096
#define NNOTES 48
#define NU 256
#define NG 1024
#define MTOT (BATCH * NNOTES)

// ==================== device scratch ====================
__device__ float g_xg0[(size_t)NNOTES * BATCH * NG];
__device__ float g_h1all[(size_t)NNOTES * BATCH * NU];
__device__ float g_c0[BATCH * NU];
__device__ float g_c1[BATCH * NU];
__device__ __align__(128) __nv_bfloat16 g_h0h[2][BATCH * NU];
__device__ __align__(128) __nv_bfloat16 g_h0l[2][BATCH * NU];
__device__ __align__(128) __nv_bfloat16 g_h1h[2][BATCH * NU];
__device__ __align__(128) __nv_bfloat16 g_h1l[2][BATCH * NU];
__device__ __align__(128) __nv_bfloat16 g_xh[(size_t)MTOT * 256];
__device__ __align__(128) __nv_bfloat16 g_xl[(size_t)MTOT * 256];
__device__ __align__(128) __nv_bfloat16 g_w0h[NG * 256], g_w0l[NG * 256];
__device__ __align__(128) __nv_bfloat16 g_whh0h[NG * 256], g_whh0l[NG * 256];
__device__ __align__(128) __nv_bfloat16 g_wcath[NG * 512], g_wcatl[NG * 512];
__device__ float g_w0ext[NG * 4];
__device__ float g_bias0[NG];
__device__ float g_bias1[NG];

__device__ __forceinline__ float sigf(float x) { return 1.0f / (1.0f + expf(-x)); }

__device__ __forceinline__ int permR(int c) {
    int W = c >> 6, cc = c & 63;
    int f = cc >> 3, r = cc & 7;
    int tig = r >> 1, e = r & 1;
    int v = (f & 3) * 4 + tig;
    int gate = (f >> 2) * 2 + e;
    int u = W * 16 + v;
    return gate * 256 + u;
}

__device__ __forceinline__ void split_bf16(float x, __nv_bfloat16& hi, __nv_bfloat16& lo) {
    hi = __float2bfloat16_rn(x);
    lo = __float2bfloat16_rn(x - __bfloat162float(hi));
}
union BF8 { __nv_bfloat16 b[8]; uint4 u; };

// ==================== prep kernels ====================
__global__ void prep_w(const float* __restrict__ W_ih0,
                       const float* __restrict__ W_hh0,
                       const float* __restrict__ W_ih1,
                       const float* __restrict__ W_hh1,
                       const float* __restrict__ b_ih0,
                       const float* __restrict__ b_hh0,
                       const float* __restrict__ b_ih1,
                       const float* __restrict__ b_hh1) {
    int tid = blockIdx.x * blockDim.x + threadIdx.x;
    int stride = gridDim.x * blockDim.x;
    for (int i = tid; i < NG * 256; i += stride) {
        int c = i >> 8, k = i & 255, R = permR(c);
        split_bf16(W_ih0[R * 259 + k], g_w0h[i], g_w0l[i]);
        split_bf16(W_hh0[R * 256 + k], g_whh0h[i], g_whh0l[i]);
    }
    for (int i = tid; i < NG * 512; i += stride) {
        int c = i >> 9, k = i & 511, R = permR(c);
        float x = (k < 256) ? W_ih1[R * 256 + k] : W_hh1[R * 256 + (k - 256)];
        split_bf16(x, g_wcath[i], g_wcatl[i]);
    }
    for (int i = tid; i < NG * 4; i += stride) {
        int c = i >> 2, t = i & 3, R = permR(c);
        g_w0ext[i] = (t < 3) ? W_ih0[R * 259 + 256 + t] : 0.0f;
    }
    for (int i = tid; i < NG; i += stride) {
        int R = permR(i);
        g_bias0[i] = b_ih0[R] + b_hh0[R];
        g_bias1[i] = b_ih1[R] + b_hh1[R];
    }
    __nv_bfloat16 z = __float2bfloat16(0.0f);
    for (int i = tid; i < BATCH * NU; i += stride) {
        g_c0[i] = 0.0f; g_c1[i] = 0.0f;
        g_h0h[0][i] = z; g_h0l[0][i] = z;
        g_h1h[0][i] = z; g_h1l[0][i] = z;
    }
}

__global__ void prep_x(const float* __restrict__ nf) {
    size_t idx = (size_t)blockIdx.x * blockDim.x + threadIdx.x;
    if (idx >= (size_t)MTOT * 32) return;
    int k8 = (int)(idx & 31) * 8;
    int m = (int)(idx >> 5);
    int b = m & 4095, nn = m >> 12;
    const float* src = nf + (((size_t)b * NNOTES + nn) << 8) + k8;
    float4 a = *(const float4*)src, c4 = *(const float4*)(src + 4);
    float v[8] = {a.x, a.y, a.z, a.w, c4.x, c4.y, c4.z, c4.w};
    BF8 hh, ll;
#pragma unroll
    for (int i = 0; i < 8; i++) split_bf16(v[i], hh.b[i], ll.b[i]);
    *(uint4*)&g_xh[(size_t)m * 256 + k8] = hh.u;
    *(uint4*)&g_xl[(size_t)m * 256 + k8] = ll.u;
}

// ==================== mma / cp.async helpers ====================
__device__ __forceinline__ uint32_t smem_u32(const void* p) {
    uint32_t a;
    asm("{ .reg .u64 t; cvta.to.shared.u64 t, %1; cvt.u32.u64 %0, t; }" : "=r"(a) : "l"(p));
    return a;
}
__device__ __forceinline__ void cpa16(uint32_t dst, const void* src) {
    asm volatile("cp.async.cg.shared.global [%0], [%1], 16;" :: "r"(dst), "l"(src) : "memory");
}
__device__ __forceinline__ void ldsm_x4(uint32_t addr, uint32_t& r0, uint32_t& r1,
                                        uint32_t& r2, uint32_t& r3) {
    asm volatile("ldmatrix.sync.aligned.m8n8.x4.shared.b16 {%0,%1,%2,%3}, [%4];"
                 : "=r"(r0), "=r"(r1), "=r"(r2), "=r"(r3) : "r"(addr));
}
__device__ __forceinline__ void mma_bf16(float* d, const uint32_t* a, const uint32_t* b) {
    asm volatile(
        "mma.sync.aligned.m16n8k16.row.col.f32.bf16.bf16.f32 "
        "{%0,%1,%2,%3},{%4,%5,%6,%7},{%8,%9},{%0,%1,%2,%3};"
        : "+f"(d[0]), "+f"(d[1]), "+f"(d[2]), "+f"(d[3])
        : "r"(a[0]), "r"(a[1]), "r"(a[2]), "r"(a[3]), "r"(b[0]), "r"(b[1]));
}

// ==================== unified GEMM body + fused LSTM epilogue ====================
// Split-2 via K-concat: C = Ah.Bh + Ah.Bl + Al.Bh as one K'=3K GEMM.
// MODE 0: xg0 = x @ W0^T + bias0 + ext (K'=768)
// MODE 1: gates = h0 @ Whh0^T + xg0[n]; LSTM -> h0,c0 (K'=768)
// MODE 2: gates = [h0|h1] @ Wcat^T + bias1; LSTM -> h1,c1,h1all (K'=1536)
#define STAGE_BYTES 20480   // A(128*80) + B(128*80)

template <int MODE>
__device__ __forceinline__ void run_gemm(const float* __restrict__ cn, int n, int mt) {
    constexpr int NCH = (MODE == 2) ? 48 : 24;
    extern __shared__ __align__(128) char dynsmem[];
    const uint32_t smem_base = smem_u32(dynsmem);

    const int t = threadIdx.x;
    const int bm = mt * 128;
    const int bn = blockIdx.x * 128;
    const int lane = t & 31, warp = t >> 5;
    const int wm = warp & 3, wn = warp >> 2;
    const int seg = t & 3, r0 = t >> 2;
    const int pPrev = n & 1, pNew = (n & 1) ^ 1;

    auto issue = [&](int ck, int s) {
        const char *Asrc, *Bsrc;
        int kkA, kkB;
        size_t bpitch;
        if (MODE == 0) {
            int term = ck >> 3, kk = (ck & 7) * 32;
            Asrc = (const char*)((term < 2) ? g_xh : g_xl);
            Bsrc = (const char*)((term == 1) ? g_w0l : g_w0h);
            kkA = kk; kkB = kk; bpitch = 512;
        } else if (MODE == 1) {
            int term = ck >> 3, kk = (ck & 7) * 32;
            Asrc = (const char*)((term < 2) ? g_h0h[pPrev] : g_h0l[pPrev]);
            Bsrc = (const char*)((term == 1) ? g_whh0l : g_whh0h);
            kkA = kk; kkB = kk; bpitch = 512;
        } else {
            int term = ck >> 4, kk = (ck & 15) * 32;
            bool lo = (term == 2);
            if (kk < 256) {
                Asrc = (const char*)(lo ? g_h0l[pNew] : g_h0h[pNew]);
                kkA = kk;
            } else {
                Asrc = (const char*)(lo ? g_h1l[pPrev] : g_h1h[pPrev]);
                kkA = kk - 256;
            }
            Bsrc = (const char*)((term == 1) ? g_wcatl : g_wcath);
            kkB = kk; bpitch = 1024;
        }
        uint32_t dA = smem_base + s * STAGE_BYTES;
        uint32_t dB = dA + 10240;
#pragma unroll
        for (int h = 0; h < 2; h++) {
            int row = r0 + h * 64;
            cpa16(dA + row * 80 + seg * 16,
                  Asrc + (size_t)(bm + row) * 512 + kkA * 2 + seg * 16);
            cpa16(dB + row * 80 + seg * 16,
                  Bsrc + (size_t)(bn + row) * bpitch + kkB * 2 + seg * 16);
        }
        asm volatile("cp.async.commit_group;" ::: "memory");
    };

    float acc[2][8][4];
#pragma unroll
    for (int mi = 0; mi < 2; mi++)
#pragma unroll
        for (int f = 0; f < 8; f++)
#pragma unroll
            for (int x = 0; x < 4; x++) acc[mi][f][x] = 0.0f;

    issue(0, 0); issue(1, 1); issue(2, 2);

    for (int ck = 0; ck < NCH; ck++) {
        int rem = NCH - 1 - ck;
        if (rem >= 2)      asm volatile("cp.async.wait_group 2;" ::: "memory");
        else if (rem == 1) asm volatile("cp.async.wait_group 1;" ::: "memory");
        else               asm volatile("cp.async.wait_group 0;" ::: "memory");
        __syncthreads();
        if (ck + 3 < NCH) issue(ck + 3, (ck + 3) & 3);

        uint32_t sAb = smem_base + (ck & 3) * STAGE_BYTES;
        uint32_t sBb = sAb + 10240;
#pragma unroll
        for (int ks = 0; ks < 2; ks++) {
            uint32_t A[2][4];
#pragma unroll
            for (int mi = 0; mi < 2; mi++) {
                uint32_t addr = sAb + (wm * 32 + mi * 16 + (lane & 15)) * 80 +
                                ks * 32 + (lane >> 4) * 16;
                ldsm_x4(addr, A[mi][0], A[mi][1], A[mi][2], A[mi][3]);
            }
            uint32_t B[4][4];
#pragma unroll
            for (int fp = 0; fp < 4; fp++) {
                uint32_t addr = sBb + (wn * 64 + fp * 16 + (lane >> 4) * 8 + (lane & 7)) * 80 +
                                ks * 32 + ((lane >> 3) & 1) * 16;
                ldsm_x4(addr, B[fp][0], B[fp][1], B[fp][2], B[fp][3]);
            }
#pragma unroll
            for (int fp = 0; fp < 4; fp++) {
#pragma unroll
                for (int mi = 0; mi < 2; mi++) {
                    mma_bf16(acc[mi][2 * fp + 0], A[mi], &B[fp][0]);
                    mma_bf16(acc[mi][2 * fp + 1], A[mi], &B[fp][2]);
                }
            }
        }
    }

    // ------------- fused epilogue -------------
    if (MODE == 0) {
        int rowm[4];
        float sv[4][3];
#pragma unroll
        for (int rid = 0; rid < 4; rid++) {
            int mi = rid >> 1, rh = rid & 1;
            int m = bm + wm * 32 + mi * 16 + rh * 8 + (lane >> 2);
            rowm[rid] = m;
            int b = m & 4095, nn = m >> 12;
            if (nn > 0) {
                const float* p = cn + ((size_t)b * NNOTES + (nn - 1)) * 3;
                sv[rid][0] = p[0]; sv[rid][1] = p[1]; sv[rid][2] = p[2];
            } else {
                sv[rid][0] = sv[rid][1] = sv[rid][2] = 0.0f;
            }
        }
#pragma unroll
        for (int f = 0; f < 8; f++) {
            int c = bn + wn * 64 + 8 * f + 2 * (lane & 3);
            float2 bia = *(const float2*)&g_bias0[c];
            float4 e0 = *(const float4*)&g_w0ext[(size_t)c * 4];
            float4 e1 = *(const float4*)&g_w0ext[(size_t)(c + 1) * 4];
#pragma unroll
            for (int rid = 0; rid < 4; rid++) {
                int mi = rid >> 1, rh = rid & 1;
                float2 o;
                o.x = acc[mi][f][rh * 2 + 0] + bia.x +
                      sv[rid][0] * e0.x + sv[rid][1] * e0.y + sv[rid][2] * e0.z;
                o.y = acc[mi][f][rh * 2 + 1] + bia.y +
                      sv[rid][0] * e1.x + sv[rid][1] * e1.y + sv[rid][2] * e1.z;
                *(float2*)&g_xg0[(size_t)rowm[rid] * NG + c] = o;
            }
        }
    } else {
#pragma unroll
        for (int rid = 0; rid < 4; rid++) {
            int mi = rid >> 1, rh = rid & 1;
            int m = bm + wm * 32 + mi * 16 + rh * 8 + (lane >> 2);
#pragma unroll
            for (int v = 0; v < 4; v++) {
                int cif = bn + wn * 64 + 8 * v + 2 * (lane & 3);
                float2 aif, ago;
                if (MODE == 1) {
                    const float* xb = g_xg0 + (size_t)n * ((size_t)BATCH * NG) + (size_t)m * NG;
                    aif = *(const float2*)&xb[cif];
                    ago = *(const float2*)&xb[cif + 32];
                } else {
                    aif = *(const float2*)&g_bias1[cif];
                    ago = *(const float2*)&g_bias1[cif + 32];
                }
                float gi = acc[mi][v][rh * 2 + 0] + aif.x;
                float gf = acc[mi][v][rh * 2 + 1] + aif.y;
                float gg = acc[mi][v + 4][rh * 2 + 0] + ago.x;
                float go = acc[mi][v + 4][rh * 2 + 1] + ago.y;
                int u = ((bn + wn * 64) >> 6) * 16 + v * 4 + (lane & 3);
                int idx = m * 256 + u;
                float* cptr = (MODE == 1) ? g_c0 : g_c1;
                float cp = cptr[idx];
                float cnew = sigf(gf) * cp + sigf(gi) * tanhf(gg);
                float h = sigf(go) * tanhf(cnew);
                cptr[idx] = cnew;
                __nv_bfloat16 hh = __float2bfloat16_rn(h);
                __nv_bfloat16 hl = __float2bfloat16_rn(h - __bfloat162float(hh));
                if (MODE == 1) {
                    g_h0h[pNew][idx] = hh; g_h0l[pNew][idx] = hl;
                } else {
                    g_h1h[pNew][idx] = hh; g_h1l[pNew][idx] = hl;
                    g_h1all[(size_t)n * (BATCH * NU) + idx] = h;
                }
            }
        }
    }
}

template <int MODE>
__global__ void __launch_bounds__(256, 2) mma_gemm(const float* __restrict__ cn, int n) {
    run_gemm<MODE>(cn, n, blockIdx.y);
}

// Combined launch: blocks [0,32) do mode2(n); blocks [32,64) do mode1(n+1).
// mode2(n) needs mode1(n) [prior launch]; mode1(n+1) needs mode1(n) [prior launch].
// Buffers: mode1(n+1) writes h0[n&1], mode2(n) reads h0[(n&1)^1] — disjoint.
__global__ void __launch_bounds__(256, 2) mma_combined(int n) {
    if (blockIdx.y < 32) run_gemm<2>(nullptr, n, blockIdx.y);
    else                 run_gemm<1>(nullptr, n + 1, blockIdx.y - 32);
}

// ==================== final projection ====================
__global__ void final_out(const float* __restrict__ Wout, const float* __restrict__ bout,
                          float* __restrict__ out) {
    int gwarp = (blockIdx.x * blockDim.x + threadIdx.x) >> 5;
    int lane = threadIdx.x & 31;
    if (gwarp >= MTOT) return;
    int b = gwarp / NNOTES, n = gwarp % NNOTES;
    const float* hrow = &g_h1all[(size_t)n * (BATCH * NU) + (size_t)b * NU];

    float s0 = 0.0f, s1 = 0.0f, s2 = 0.0f;
    int u = lane * 8;
    float4 v0 = *(const float4*)&hrow[u];
    float4 v1 = *(const float4*)&hrow[u + 4];
    float hv[8] = {v0.x, v0.y, v0.z, v0.w, v1.x, v1.y, v1.z, v1.w};
#pragma unroll
    for (int i = 0; i < 8; i++) {
        float h = hv[i];
        s0 += h * Wout[0 * NU + u + i];
        s1 += h * Wout[1 * NU + u + i];
        s2 += h * Wout[2 * NU + u + i];
    }
#pragma unroll
    for (int off = 16; off > 0; off >>= 1) {
        s0 += __shfl_xor_sync(0xffffffffu, s0, off);
        s1 += __shfl_xor_sync(0xffffffffu, s1, off);
        s2 += __shfl_xor_sync(0xffffffffu, s2, off);
    }
    if (lane == 0) {
        float* o = &out[(size_t)b * (NNOTES * 3) + (size_t)n * 3];
        o[0] = sigf(s0 + bout[0]);
        o[1] = sigf(s1 + bout[1]);
        o[2] = s2 + bout[2];
    }
}

// ==================== launch ====================
extern "C" void kernel_launch(void* const* d_in, const int* in_sizes, int n_in,
                              void* d_out, int out_size) {
    const float* nf    = (const float*)d_in[0];
    const float* cn    = (const float*)d_in[1];
    const float* W_ih0 = (const float*)d_in[2];
    const float* W_hh0 = (const float*)d_in[3];
    const float* b_ih0 = (const float*)d_in[4];
    const float* b_hh0 = (const float*)d_in[5];
    const float* W_ih1 = (const float*)d_in[6];
    const float* W_hh1 = (const float*)d_in[7];
    const float* b_ih1 = (const float*)d_in[8];
    const float* b_hh1 = (const float*)d_in[9];
    const float* W_out = (const float*)d_in[10];
    const float* b_out = (const float*)d_in[11];
    float* out = (float*)d_out;

    const int DYNSMEM = 4 * STAGE_BYTES;  // 81920
    cudaFuncSetAttribute(mma_gemm<0>, cudaFuncAttributeMaxDynamicSharedMemorySize, DYNSMEM);
    cudaFuncSetAttribute(mma_gemm<1>, cudaFuncAttributeMaxDynamicSharedMemorySize, DYNSMEM);
    cudaFuncSetAttribute(mma_gemm<2>, cudaFuncAttributeMaxDynamicSharedMemorySize, DYNSMEM);
    cudaFuncSetAttribute(mma_combined, cudaFuncAttributeMaxDynamicSharedMemorySize, DYNSMEM);

    prep_w<<<1024, 256>>>(W_ih0, W_hh0, W_ih1, W_hh1, b_ih0, b_hh0, b_ih1, b_hh1);
    prep_x<<<(MTOT * 32 + 255) / 256, 256>>>(nf);

    // layer-0 input GEMM over all notes
    mma_gemm<0><<<dim3(NG / 128, MTOT / 128), 256, DYNSMEM>>>(cn, 0);

    // recurrence: mode1(0); then {mode2(n) || mode1(n+1)} for n=0..46; then mode2(47)
    mma_gemm<1><<<dim3(8, 32), 256, DYNSMEM>>>(nullptr, 0);
    for (int n = 0; n < NNOTES - 1; n++)
        mma_combined<<<dim3(8, 64), 256, DYNSMEM>>>(n);
    mma_gemm<2><<<dim3(8, 32), 256, DYNSMEM>>>(nullptr, NNOTES - 1);

    int blocks = (MTOT * 32 + 255) / 256;
    final_out<<<blocks, 256>>>(W_out, b_out, out);
}